// round 17
// baseline (speedup 1.0000x reference)
#include <cuda_runtime.h>
#include <cuda_bf16.h>
#include <math.h>
#include <stdint.h>

#define CN 128
#define SS 56
#define NPX (SS * SS)          // 3136
#define NTAP 36
#define NT40 40                // padded tap count (mma N dim)
#define QPITCH 3200            // padded pixels per Q plane (>= 3168+32 tile slack)
#define TILE_M 128
#define NTILES 25              // ceil(3136/128)

// ---------------------------------------------------------------------------
// intrinsics
// ---------------------------------------------------------------------------
__device__ __forceinline__ float fast_lg2(float v) {
    float r; asm("lg2.approx.f32 %0, %1;" : "=f"(r) : "f"(v)); return r;
}
__device__ __forceinline__ float fast_ex2(float v) {
    float r; asm("ex2.approx.f32 %0, %1;" : "=f"(r) : "f"(v)); return r;
}
// pack two f32 -> bf16x2; lo half = second operand
__device__ __forceinline__ unsigned bf16x2(float hi, float lo) {
    unsigned r; asm("cvt.rn.bf16x2.f32 %0, %1, %2;" : "=r"(r) : "f"(hi), "f"(lo));
    return r;
}
// D(16x8) += A(16x16,row,bf16) * B(16x8,col,bf16), f32 accum
__device__ __forceinline__ void mma16(float* c, const unsigned* a,
                                      unsigned b0, unsigned b1) {
    asm volatile(
        "mma.sync.aligned.m16n8k16.row.col.f32.bf16.bf16.f32 "
        "{%0,%1,%2,%3}, {%4,%5,%6,%7}, {%8,%9}, {%0,%1,%2,%3};"
        : "+f"(c[0]), "+f"(c[1]), "+f"(c[2]), "+f"(c[3])
        : "r"(a[0]), "r"(a[1]), "r"(a[2]), "r"(a[3]), "r"(b0), "r"(b1));
}

// ---------------------------------------------------------------------------
// scratch (device globals are zero-initialized; pads stay 0)
// ---------------------------------------------------------------------------
__device__ float d_bankU[CN * CN * NT40];           // [i][u][t40], t pads = 0
__device__ float d_biasn[CN];
__device__ float d_Q[2 * CN * NTAP * QPITCH];       // Q[bi][t][px], 118 MB (< L2)

// ---------------------------------------------------------------------------
// Kernel 1: gaussian bank (u-major, t-padded) + bias^nU
// ---------------------------------------------------------------------------
__global__ void bank_kernel(const float* __restrict__ theta,
                            const float* __restrict__ p,
                            const float* __restrict__ sig,
                            const float* __restrict__ a,
                            const float* __restrict__ bias,
                            const float* __restrict__ nU) {
    int g = blockIdx.x * blockDim.x + threadIdx.x;
    if (g >= CN * CN * NTAP) return;
    int iu = g / NTAP;
    int t  = g - iu * NTAP;
    int r = t / 6;
    int c = t - r * 6;

    float th = theta[iu];
    float pv = p[iu];
    float sg = sig[iu];
    float av = a[iu];
    float st, ct;
    sincosf(th, &st, &ct);   // theta up to ~300 rad -> precise path
    float amp = av / (2.0f * 3.14159265358979323846f * pv * sg);
    float ip2 = 1.0f / (pv * pv);
    float is2 = 1.0f / (sg * sg);

    float xv = -3.0f + 1.2f * (float)r;
    float yv = -3.0f + 1.2f * (float)c;
    float xr = xv * ct + yv * st;
    float yr = -xv * st + yv * ct;
    d_bankU[iu * NT40 + t] = amp * expf(-0.5f * (xr * xr * ip2 + yr * yr * is2));

    if (g < CN) d_biasn[g] = powf(bias[g], nU[g]);
}

// ---------------------------------------------------------------------------
// Kernel 2: per (b,i,tile) — Q[px,t] = P[px,u] · G[t,u]^T via mma.sync bf16
// 128 threads = 4 warps; warp w owns px rows [tile*128 + w*32, +32)
// ---------------------------------------------------------------------------
__global__ __launch_bounds__(128) void mma_kernel(const float* __restrict__ x,
                                                  const float* __restrict__ nI) {
    __shared__ unsigned sBp[(CN / 2) * NT40];   // bf16x2 u-pairs: [pair][t]
    __shared__ float sNI[CN];

    const int cta  = blockIdx.x;
    const int tile = cta % NTILES;
    const int bi   = cta / NTILES;
    const int i    = bi & (CN - 1);
    const int tid  = threadIdx.x;
    const int w    = tid >> 5;
    const int lane = tid & 31;
    const int lk   = lane & 3;           // thread-in-group
    const int lg   = lane >> 2;          // group (row idx)

    // fill B pairs: (g[2p][t] lo, g[2p+1][t] hi) as bf16x2
    const float* bu = d_bankU + i * CN * NT40;
    for (int e = tid; e < (CN / 2) * NT40; e += 128) {
        int pr = e / NT40;
        int t  = e - pr * NT40;
        sBp[e] = bf16x2(bu[(2 * pr + 1) * NT40 + t], bu[(2 * pr) * NT40 + t]);
    }
    if (tid < CN) sNI[tid] = nI[i * CN + tid];

    // per-thread log2(x) at its 4 fragment rows
    const int pxb = tile * TILE_M + w * 32;
    float L[4];
    #pragma unroll
    for (int rr = 0; rr < 4; rr++) {
        int px = pxb + lg + 8 * rr;
        L[rr] = (px < NPX) ? fast_lg2(x[bi * NPX + px]) : 0.0f;
    }
    __syncthreads();

    float acc[2][5][4];
    #pragma unroll
    for (int mt = 0; mt < 2; mt++)
        #pragma unroll
        for (int nt = 0; nt < 5; nt++)
            #pragma unroll
            for (int q = 0; q < 4; q++) acc[mt][nt][q] = 0.0f;

    #pragma unroll
    for (int kt = 0; kt < 8; kt++) {      // K = 128 = 8 x 16
        // u indices this thread contributes: kt*16 + {2lk, 2lk+1, 2lk+8, 2lk+9}
        float na = sNI[kt * 16 + 2 * lk];
        float nb = sNI[kt * 16 + 2 * lk + 1];
        float nc = sNI[kt * 16 + 2 * lk + 8];
        float nd = sNI[kt * 16 + 2 * lk + 9];
        unsigned a[2][4];
        #pragma unroll
        for (int mt = 0; mt < 2; mt++) {
            float L0 = L[2 * mt];         // row lg
            float L1 = L[2 * mt + 1];     // row lg+8
            a[mt][0] = bf16x2(fast_ex2(nb * L0), fast_ex2(na * L0));
            a[mt][1] = bf16x2(fast_ex2(nb * L1), fast_ex2(na * L1));
            a[mt][2] = bf16x2(fast_ex2(nd * L0), fast_ex2(nc * L0));
            a[mt][3] = bf16x2(fast_ex2(nd * L1), fast_ex2(nc * L1));
        }
        #pragma unroll
        for (int nt = 0; nt < 5; nt++) {
            unsigned b0 = sBp[(kt * 8 + lk) * NT40 + nt * 8 + lg];      // k=2lk,2lk+1
            unsigned b1 = sBp[(kt * 8 + lk + 4) * NT40 + nt * 8 + lg];  // k=2lk+8,+9
            mma16(acc[0][nt], a[0], b0, b1);
            mma16(acc[1][nt], a[1], b0, b1);
        }
    }

    // store D -> Q[bi][t][px]; only t < 36 planes exist
    float* q = d_Q + (size_t)bi * NTAP * QPITCH;
    #pragma unroll
    for (int mt = 0; mt < 2; mt++) {
        int r_lo = pxb + mt * 16 + lg;
        int r_hi = r_lo + 8;
        #pragma unroll
        for (int nt = 0; nt < 5; nt++) {
            int t0 = nt * 8 + lk * 2;
            if (t0 < NTAP) {
                q[(size_t)t0 * QPITCH + r_lo]       = acc[mt][nt][0];
                q[(size_t)(t0 + 1) * QPITCH + r_lo] = acc[mt][nt][1];
                q[(size_t)t0 * QPITCH + r_hi]       = acc[mt][nt][2];
                q[(size_t)(t0 + 1) * QPITCH + r_hi] = acc[mt][nt][3];
            }
        }
    }
}

// ---------------------------------------------------------------------------
// Kernel 3: shift-gather over 36 taps + combine
// out = x^nU / (bias^nU + sum_t Q[t][shifted])
// ---------------------------------------------------------------------------
__global__ void gather_kernel(const float* __restrict__ x,
                              const float* __restrict__ nU,
                              float* __restrict__ out, int total) {
    int idx = blockIdx.x * blockDim.x + threadIdx.x;
    if (idx >= total) return;
    int px = idx % NPX;
    int bi = idx / NPX;
    int i  = bi & (CN - 1);
    int y  = px / SS;
    int xx = px - y * SS;

    const float* q = d_Q + (size_t)bi * NTAP * QPITCH;
    float sum = 0.0f;
    #pragma unroll
    for (int r = 0; r < 6; r++) {
        int yy = y + r - 2;
        if ((unsigned)yy < SS) {
            #pragma unroll
            for (int c = 0; c < 6; c++) {
                int xc = xx + c - 2;
                if ((unsigned)xc < SS)
                    sum += q[(size_t)(r * 6 + c) * QPITCH + yy * SS + xc];
            }
        }
    }
    float num = fast_ex2(nU[i] * fast_lg2(x[idx]));
    out[idx] = num / (d_biasn[i] + sum);
}

// ---------------------------------------------------------------------------
extern "C" void kernel_launch(void* const* d_in, const int* in_sizes, int n_in,
                              void* d_out, int out_size) {
    const float* x     = (const float*)d_in[0];
    const float* theta = (const float*)d_in[1];
    const float* p     = (const float*)d_in[2];
    const float* sig   = (const float*)d_in[3];
    const float* a     = (const float*)d_in[4];
    const float* nI    = (const float*)d_in[5];
    const float* nU    = (const float*)d_in[6];
    const float* bias  = (const float*)d_in[7];
    float* out = (float*)d_out;

    int B = in_sizes[0] / (CN * NPX);   // = 2

    bank_kernel<<<(CN * CN * NTAP + 255) / 256, 256>>>(theta, p, sig, a, bias, nU);
    mma_kernel<<<B * CN * NTILES, 128>>>(x, nI);
    gather_kernel<<<(out_size + 255) / 256, 256>>>(x, nU, out, out_size);
}